// round 13
// baseline (speedup 1.0000x reference)
#include <cuda_runtime.h>
#include <cuda_bf16.h>
#include <math.h>
#include <stdint.h>

#define NN 65536
#define GG 128
#define LL 512
#define DD 128
#define EE 262144
#define NSTEPS 6
#define CC 256
#define L1OUT 510   // conv K=3 valid out length
#define P1OUT 254   // pool (3,2) out
#define P2OUT 127   // pool (2,2) out

// ---------------- scratch (device globals; no allocs allowed) ----------------
__device__ float g_h[NN * DD];
__device__ float g_m[NN * DD];
__device__ float g_agg[NN * DD];
__device__ float g_gx[NN * 3 * DD];
__device__ float g_gh[NN * 3 * DD];
__device__ float g_c[NN * CC];
__device__ float g_wT[NSTEPS * DD * DD];
__device__ float g_w1p[3 * DD * DD];
__device__ float g_wc1p[3 * CC * CC];
__device__ float g_convY1[NN * DD];            // [G,512,D] padded length
__device__ float g_poolY1[GG * P1OUT * DD];
__device__ float g_convY2[GG * P1OUT * DD];
__device__ float g_poolY2[GG * P2OUT * DD];
__device__ float g_convZ1[NN * CC];            // [G,512,C] padded length
__device__ float g_poolZ1[GG * P1OUT * CC];
__device__ float g_convZ2[GG * P1OUT * CC];
__device__ float g_poolZ2[GG * P2OUT * CC];
__device__ float g_stats[512];                 // per-channel sum / sumsq

// bf16 hi/lo weight store
#define WB_WT   0
#define WB_WIH  98304
#define WB_WHH  147456
#define WB_W1P  196608
#define WB_CW2  245760
#define WB_WC1  262144
#define WB_CW2C 458752
#define WB_TOT  524288
__device__ __align__(16) __nv_bfloat16 g_wbhi[WB_TOT];
__device__ __align__(16) __nv_bfloat16 g_wblo[WB_TOT];

// CSR scratch
__device__ int g_counts[NN];
__device__ int g_cursor[NN];
__device__ int g_bsum[256];
__device__ int g_rowptr[NN + 1];
__device__ int g_csrc[EE];
__device__ float g_cw[EE];

// ---------------- bf16 helpers ----------------
__device__ __forceinline__ unsigned bfpack(float hi_src, float lo_src) {
    unsigned r;
    asm("cvt.rn.bf16x2.f32 %0, %1, %2;" : "=r"(r) : "f"(hi_src), "f"(lo_src));
    return r;
}
__device__ __forceinline__ unsigned pack_bf2(__nv_bfloat16 a, __nv_bfloat16 b) {
    return (unsigned)__bfloat16_as_ushort(a) | ((unsigned)__bfloat16_as_ushort(b) << 16);
}
__device__ __forceinline__ void mma_bf16(float* d, const unsigned* a, const unsigned* b) {
    asm("mma.sync.aligned.m16n8k16.row.col.f32.bf16.bf16.f32 "
        "{%0,%1,%2,%3}, {%4,%5,%6,%7}, {%8,%9}, {%0,%1,%2,%3};"
        : "+f"(d[0]), "+f"(d[1]), "+f"(d[2]), "+f"(d[3])
        : "r"(a[0]), "r"(a[1]), "r"(a[2]), "r"(a[3]), "r"(b[0]), "r"(b[1]));
}

// ---------------- small utility kernels ----------------
__global__ void fill_zero4(float4* p, long n4) {
    long i = (long)blockIdx.x * blockDim.x + threadIdx.x;
    if (i < n4) p[i] = make_float4(0.f, 0.f, 0.f, 0.f);
}
__global__ void copy_f4(float4* dst, const float4* src, long n4) {
    long i = (long)blockIdx.x * blockDim.x + threadIdx.x;
    if (i < n4) dst[i] = src[i];
}
__global__ void transpose_ggnn(const float* __restrict__ w, float* __restrict__ wT) {
    int t = blockIdx.x * blockDim.x + threadIdx.x;
    if (t >= NSTEPS * DD * DD) return;
    int s = t / (DD * DD);
    int rem = t - s * (DD * DD);
    int j = rem / DD, k = rem - (rem / DD) * DD;
    wT[t] = w[s * DD * DD + k * DD + j];
}
__global__ void pack_conv3(const float* __restrict__ w, float* __restrict__ wp, int Ch) {
    int t = blockIdx.x * blockDim.x + threadIdx.x;
    int total = 3 * Ch * Ch;
    if (t >= total) return;
    int k = t / (Ch * Ch);
    int rem = t - k * (Ch * Ch);
    int o = rem / Ch, i = rem - (rem / Ch) * Ch;
    wp[t] = w[(o * Ch + i) * 3 + k];
}
// fp32 -> bf16 hi + lo residual (rn rounding, identical to in-kernel cvt1)
__global__ void split_bf16(const float4* __restrict__ src, uint2* __restrict__ hi,
                           uint2* __restrict__ lo, long n4) {
    long i = (long)blockIdx.x * blockDim.x + threadIdx.x;
    if (i >= n4) return;
    float4 v = src[i];
    __nv_bfloat16 bx = __float2bfloat16(v.x), by = __float2bfloat16(v.y);
    __nv_bfloat16 bz = __float2bfloat16(v.z), bw = __float2bfloat16(v.w);
    __nv_bfloat16 rx = __float2bfloat16(v.x - __bfloat162float(bx));
    __nv_bfloat16 ry = __float2bfloat16(v.y - __bfloat162float(by));
    __nv_bfloat16 rz = __float2bfloat16(v.z - __bfloat162float(bz));
    __nv_bfloat16 rw = __float2bfloat16(v.w - __bfloat162float(bw));
    hi[i] = make_uint2(pack_bf2(bx, by), pack_bf2(bz, bw));
    lo[i] = make_uint2(pack_bf2(rx, ry), pack_bf2(rz, rw));
}
// c[i] = [h[i], x[i]]
__global__ void concat_kernel(const float4* __restrict__ h, const float4* __restrict__ x,
                              float4* __restrict__ c) {
    long t = (long)blockIdx.x * blockDim.x + threadIdx.x;
    if (t >= (long)NN * (DD / 4)) return;
    long i = t >> 5;
    int d = (int)(t & 31);
    c[i * (CC / 4) + d] = h[t];
    c[i * (CC / 4) + (DD / 4) + d] = x[t];
}

// ---------------- CSR build ----------------
__global__ void hist_kernel(const int* __restrict__ ei, int* __restrict__ counts) {
    int e = blockIdx.x * 256 + threadIdx.x;
    if (e < EE) atomicAdd(&counts[ei[EE + e]], 1);
}
__global__ void scan_block(const int* __restrict__ counts, int* __restrict__ excl,
                           int* __restrict__ bsum) {
    __shared__ int sh[256];
    int i = blockIdx.x * 256 + threadIdx.x;
    int v = counts[i];
    sh[threadIdx.x] = v;
    __syncthreads();
    for (int d = 1; d < 256; d <<= 1) {
        int t = (threadIdx.x >= d) ? sh[threadIdx.x - d] : 0;
        __syncthreads();
        sh[threadIdx.x] += t;
        __syncthreads();
    }
    excl[i] = sh[threadIdx.x] - v;
    if (threadIdx.x == 255) bsum[blockIdx.x] = sh[255];
}
__global__ void scan_bsum(int* __restrict__ bsum) {
    __shared__ int sh[256];
    int v = bsum[threadIdx.x];
    sh[threadIdx.x] = v;
    __syncthreads();
    for (int d = 1; d < 256; d <<= 1) {
        int t = (threadIdx.x >= d) ? sh[threadIdx.x - d] : 0;
        __syncthreads();
        sh[threadIdx.x] += t;
        __syncthreads();
    }
    bsum[threadIdx.x] = sh[threadIdx.x] - v;   // exclusive
}
__global__ void scan_add(int* __restrict__ rowptr, const int* __restrict__ bsum) {
    int i = blockIdx.x * 256 + threadIdx.x;
    rowptr[i] += bsum[blockIdx.x];
    if (i == 0) rowptr[NN] = EE;
}
__global__ void fill_csr(const int* __restrict__ ei, const float* __restrict__ ew,
                         const int* __restrict__ rowptr, int* __restrict__ cursor,
                         int* __restrict__ csrc, float* __restrict__ cw) {
    int e = blockIdx.x * 256 + threadIdx.x;
    if (e >= EE) return;
    int d = ei[EE + e];
    int pos = rowptr[d] + atomicAdd(&cursor[d], 1);
    csrc[pos] = ei[e];
    cw[pos] = ew[e];
}
// gather: one warp per node (32 consecutive threads), each lane = 4 channels
__global__ void gather_kernel(const float* __restrict__ m, const int* __restrict__ rowptr,
                              const int* __restrict__ csrc, const float* __restrict__ cw,
                              float* __restrict__ agg) {
    long t = (long)blockIdx.x * blockDim.x + threadIdx.x;
    if (t >= (long)NN * 32) return;
    int n = (int)(t >> 5);
    int q = (int)(t & 31) * 4;
    int beg = rowptr[n], end = rowptr[n + 1];
    float4 s = make_float4(0.f, 0.f, 0.f, 0.f);
    for (int j = beg; j < end; j++) {
        int src = csrc[j];
        float w = cw[j];
        float4 v = *(const float4*)(m + (size_t)src * DD + q);
        s.x += v.x * w; s.y += v.y * w; s.z += v.z * w; s.w += v.w * w;
    }
    *(float4*)(agg + (size_t)n * DD + q) = s;
}

// ---------------- 3xBF16-split GEMM: A fp32 (split in-kernel), B pre-split ----
// C[M,Nc] = A[M,K] @ B[Nc,K]^T (+bias)(+acc). 128x128 tile, k16 stages,
// 256 threads (8 warps = 4M x 2N), warp tile 32x64, per-nf interleaved 3 MMAs
// (R8-proven order). B-side tiles are direct bf16 hi/lo LDG.64 -> STS.64
// (no cvt ALU, half the LDG bytes). Smem stride-12 rows, conflict-free.
#define BM 128
#define BN 128
#define SPITCH 12
__global__ void __launch_bounds__(256, 2) gemm_bf16s(
    const float* __restrict__ A,
    const __nv_bfloat16* __restrict__ Bhi, const __nv_bfloat16* __restrict__ Blo,
    const float* __restrict__ bias, float* __restrict__ Cmat,
    int M, int Nc, int K, int validA, int accFlag)
{
    __shared__ __align__(16) unsigned Ah[2][BM * SPITCH];
    __shared__ __align__(16) unsigned Al[2][BM * SPITCH];
    __shared__ __align__(16) unsigned Bh[2][BN * SPITCH];
    __shared__ __align__(16) unsigned Bl[2][BN * SPITCH];
    int bm = blockIdx.x * BM;
    int bn = blockIdx.y * BN;
    int tid = threadIdx.x;
    int lane = tid & 31;
    int wid = tid >> 5;
    int warpM = wid & 3;            // 0..3 -> 32-row slab
    int warpN = wid >> 2;           // 0..1 -> 64-col slab
    int qr = lane >> 2;             // 0..7
    int qk = lane & 3;              // 0..3
    int lr = tid >> 2;              // 0..63 load row
    int lk4 = (tid & 3) * 4;        // k sub-offset (4 elements)
    int kp0 = lk4 >> 1;             // bf16x2 word index {0,2,4,6}

    const float4 z4 = make_float4(0.f, 0.f, 0.f, 0.f);
    const uint2 z2 = make_uint2(0u, 0u);
    const float* pa0 = A + (size_t)(bm + lr) * K + lk4;
    const float* pa1 = A + (size_t)(bm + 64 + lr) * K + lk4;
    const __nv_bfloat16* pbh0 = Bhi + (size_t)(bn + lr) * K + lk4;
    const __nv_bfloat16* pbh1 = Bhi + (size_t)(bn + 64 + lr) * K + lk4;
    const __nv_bfloat16* pbl0 = Blo + (size_t)(bn + lr) * K + lk4;
    const __nv_bfloat16* pbl1 = Blo + (size_t)(bn + 64 + lr) * K + lk4;
    bool okA0 = (bm + lr) < validA;
    bool okA1 = (bm + 64 + lr) < validA;
    bool okB0 = (bn + lr) < Nc;
    bool okB1 = (bn + 64 + lr) < Nc;

    float4 rA0, rA1;
    uint2 rBh0, rBh1, rBl0, rBl1;

    auto loadRegs = [&](int off) {
        rA0 = okA0 ? *(const float4*)(pa0 + off) : z4;
        rA1 = okA1 ? *(const float4*)(pa1 + off) : z4;
        rBh0 = okB0 ? *(const uint2*)(pbh0 + off) : z2;
        rBh1 = okB1 ? *(const uint2*)(pbh1 + off) : z2;
        rBl0 = okB0 ? *(const uint2*)(pbl0 + off) : z2;
        rBl1 = okB1 ? *(const uint2*)(pbl1 + off) : z2;
    };
    auto cvt1 = [&](float4 v, unsigned* dh, unsigned* dl) {
        unsigned h0 = bfpack(v.y, v.x);
        unsigned h1 = bfpack(v.w, v.z);
        float hx = __uint_as_float(h0 << 16);
        float hy = __uint_as_float(h0 & 0xffff0000u);
        float hz = __uint_as_float(h1 << 16);
        float hw = __uint_as_float(h1 & 0xffff0000u);
        unsigned l0 = bfpack(v.y - hy, v.x - hx);
        unsigned l1 = bfpack(v.w - hw, v.z - hz);
        *(uint2*)dh = make_uint2(h0, h1);
        *(uint2*)dl = make_uint2(l0, l1);
    };
    auto storeStage = [&](int buf) {
        cvt1(rA0, &Ah[buf][lr * SPITCH + kp0], &Al[buf][lr * SPITCH + kp0]);
        cvt1(rA1, &Ah[buf][(64 + lr) * SPITCH + kp0], &Al[buf][(64 + lr) * SPITCH + kp0]);
        *(uint2*)&Bh[buf][lr * SPITCH + kp0] = rBh0;
        *(uint2*)&Bh[buf][(64 + lr) * SPITCH + kp0] = rBh1;
        *(uint2*)&Bl[buf][lr * SPITCH + kp0] = rBl0;
        *(uint2*)&Bl[buf][(64 + lr) * SPITCH + kp0] = rBl1;
    };

    float acc[2][8][4];
    #pragma unroll
    for (int i = 0; i < 2; i++)
        #pragma unroll
        for (int j = 0; j < 8; j++)
            #pragma unroll
            for (int p = 0; p < 4; p++) acc[i][j][p] = 0.f;

    int ksteps = K >> 4;
    loadRegs(0);
    storeStage(0);
    __syncthreads();

    for (int kt = 0; kt < ksteps; kt++) {
        int cur = kt & 1;
        int nxt = cur ^ 1;
        bool more = (kt + 1 < ksteps);
        if (more) loadRegs((kt + 1) * 16);   // LDG early: latency under MMAs

        const unsigned* cAh = Ah[cur];
        const unsigned* cAl = Al[cur];
        const unsigned* cBh = Bh[cur];
        const unsigned* cBl = Bl[cur];

        unsigned ahi[2][4], alo[2][4];
        #pragma unroll
        for (int mf = 0; mf < 2; mf++) {
            int r = warpM * 32 + mf * 16 + qr;
            ahi[mf][0] = cAh[r * SPITCH + qk];
            ahi[mf][1] = cAh[(r + 8) * SPITCH + qk];
            ahi[mf][2] = cAh[r * SPITCH + qk + 4];
            ahi[mf][3] = cAh[(r + 8) * SPITCH + qk + 4];
            alo[mf][0] = cAl[r * SPITCH + qk];
            alo[mf][1] = cAl[(r + 8) * SPITCH + qk];
            alo[mf][2] = cAl[r * SPITCH + qk + 4];
            alo[mf][3] = cAl[(r + 8) * SPITCH + qk + 4];
        }
        #pragma unroll
        for (int nf = 0; nf < 8; nf++) {
            int cn = warpN * 64 + nf * 8 + qr;
            unsigned bhi[2], blo[2];
            bhi[0] = cBh[cn * SPITCH + qk];
            bhi[1] = cBh[cn * SPITCH + qk + 4];
            blo[0] = cBl[cn * SPITCH + qk];
            blo[1] = cBl[cn * SPITCH + qk + 4];
            #pragma unroll
            for (int mf = 0; mf < 2; mf++) {
                mma_bf16(acc[mf][nf], ahi[mf], bhi);   // hi*hi
                mma_bf16(acc[mf][nf], alo[mf], bhi);   // lo*hi
                mma_bf16(acc[mf][nf], ahi[mf], blo);   // hi*lo
            }
        }

        if (more) storeStage(nxt);   // cvt(A)+STS while tensor pipe drains
        __syncthreads();
    }

    // ---- epilogue ----
    #pragma unroll
    for (int mf = 0; mf < 2; mf++) {
        int row0 = bm + warpM * 32 + mf * 16 + qr;
        #pragma unroll
        for (int nf = 0; nf < 8; nf++) {
            int col = bn + warpN * 64 + nf * 8 + qk * 2;
            float b0 = 0.f, b1 = 0.f;
            if (bias) { b0 = bias[col]; b1 = bias[col + 1]; }
            #pragma unroll
            for (int hh = 0; hh < 2; hh++) {
                int row = row0 + hh * 8;
                if (row >= M) continue;
                float v0 = acc[mf][nf][hh * 2 + 0] + b0;
                float v1 = acc[mf][nf][hh * 2 + 1] + b1;
                float* cp = Cmat + (size_t)row * Nc + col;
                if (accFlag) {
                    float2 c0 = *(const float2*)cp;
                    v0 += c0.x; v1 += c0.y;
                }
                *(float2*)cp = make_float2(v0, v1);
            }
        }
    }
}

// ---------------- GRU ----------------
__global__ void gru_kernel(const float4* __restrict__ gx, const float4* __restrict__ gh,
                           float4* __restrict__ h) {
    long t = (long)blockIdx.x * blockDim.x + threadIdx.x;
    if (t >= (long)NN * (DD / 4)) return;
    long i = t >> 5;
    int d = (int)(t & 31);
    long base = i * (3 * DD / 4);
    float4 xr = gx[base + d], xz = gx[base + 32 + d], xn = gx[base + 64 + d];
    float4 hr = gh[base + d], hz = gh[base + 32 + d], hn = gh[base + 64 + d];
    float4 hold = h[t];
    float4 outv;
    {
        float r = 1.f / (1.f + expf(-(xr.x + hr.x)));
        float z = 1.f / (1.f + expf(-(xz.x + hz.x)));
        float n = tanhf(xn.x + r * hn.x);
        outv.x = (1.f - z) * n + z * hold.x;
    }
    {
        float r = 1.f / (1.f + expf(-(xr.y + hr.y)));
        float z = 1.f / (1.f + expf(-(xz.y + hz.y)));
        float n = tanhf(xn.y + r * hn.y);
        outv.y = (1.f - z) * n + z * hold.y;
    }
    {
        float r = 1.f / (1.f + expf(-(xr.z + hr.z)));
        float z = 1.f / (1.f + expf(-(xz.z + hz.z)));
        float n = tanhf(xn.z + r * hn.z);
        outv.z = (1.f - z) * n + z * hold.z;
    }
    {
        float r = 1.f / (1.f + expf(-(xr.w + hr.w)));
        float z = 1.f / (1.f + expf(-(xz.w + hz.w)));
        float n = tanhf(xn.w + r * hn.w);
        outv.w = (1.f - z) * n + z * hold.w;
    }
    h[t] = outv;
}

// ---------------- BN stats + fused BN/ReLU/maxpool ----------------
__global__ void stats_kernel(const float* __restrict__ X, float* __restrict__ stats,
                             int Lvalid, int Lpad, int Ch, int rowsPerBlock) {
    int c = threadIdx.x;
    float s = 0.f, sq = 0.f;
    int base = blockIdx.x * rowsPerBlock;
    int total = GG * Lvalid;
    for (int i = 0; i < rowsPerBlock; i++) {
        int vr = base + i;
        if (vr >= total) break;
        int g = vr / Lvalid;
        int l = vr - g * Lvalid;
        float v = X[((size_t)(g * Lpad + l)) * Ch + c];
        s += v; sq += v * v;
    }
    atomicAdd(&stats[c], s);
    atomicAdd(&stats[Ch + c], sq);
}

__global__ void bn_relu_pool(const float4* __restrict__ X, float4* __restrict__ Yout,
                             const float* __restrict__ stats, const float* __restrict__ gamma,
                             const float* __restrict__ beta, int Ch, int Lpad, int Lout,
                             int win, int stride, float inv_cnt) {
    long idx = (long)blockIdx.x * blockDim.x + threadIdx.x;
    int ch4 = Ch >> 2;
    long total = (long)GG * Lout * ch4;
    if (idx >= total) return;
    int c4 = (int)(idx % ch4);
    long r = idx / ch4;
    int lp = (int)(r % Lout);
    int g = (int)(r / Lout);
    int c = c4 * 4;
    float sc[4], sh[4];
    #pragma unroll
    for (int j = 0; j < 4; j++) {
        float mean = stats[c + j] * inv_cnt;
        float var = stats[Ch + c + j] * inv_cnt - mean * mean;
        sc[j] = rsqrtf(var + 1e-5f) * gamma[c + j];
        sh[j] = beta[c + j] - mean * sc[j];
    }
    float4 mx = make_float4(0.f, 0.f, 0.f, 0.f);
    for (int j = 0; j < win; j++) {
        int l = lp * stride + j;
        float4 v = X[((size_t)(g * Lpad + l)) * ch4 + c4];
        mx.x = fmaxf(mx.x, v.x * sc[0] + sh[0]);
        mx.y = fmaxf(mx.y, v.y * sc[1] + sh[1]);
        mx.z = fmaxf(mx.z, v.z * sc[2] + sh[2]);
        mx.w = fmaxf(mx.w, v.w * sc[3] + sh[3]);
    }
    Yout[((size_t)(g * Lout + lp)) * ch4 + c4] = mx;
}

// ---------------- final ----------------
__global__ void __launch_bounds__(128) final_kernel(
    const float* __restrict__ Y2, const float* __restrict__ Z2,
    const float* __restrict__ wy, const float* __restrict__ by,
    const float* __restrict__ wz, const float* __restrict__ bz,
    float* __restrict__ out)
{
    int g = blockIdx.x, tid = threadIdx.x;
    __shared__ float swy[2 * DD];
    __shared__ float swz[2 * CC];
    __shared__ float red0[128], red1[128];
    for (int i = tid; i < 2 * DD; i += 128) swy[i] = wy[i];
    for (int i = tid; i < 2 * CC; i += 128) swz[i] = wz[i];
    __syncthreads();
    float a0 = 0.f, a1 = 0.f;
    if (tid < P2OUT) {
        const float* yr = Y2 + ((size_t)g * P2OUT + tid) * DD;
        const float* zr = Z2 + ((size_t)g * P2OUT + tid) * CC;
        float y0 = by[0], y1 = by[1], z0 = bz[0], z1 = bz[1];
        for (int d = 0; d < DD; d++) { float v = yr[d]; y0 += v * swy[d]; y1 += v * swy[DD + d]; }
        for (int d = 0; d < CC; d++) { float v = zr[d]; z0 += v * swz[d]; z1 += v * swz[CC + d]; }
        a0 = y0 * z0;
        a1 = y1 * z1;
    }
    red0[tid] = a0; red1[tid] = a1;
    __syncthreads();
    for (int s = 64; s > 0; s >>= 1) {
        if (tid < s) { red0[tid] += red0[tid + s]; red1[tid] += red1[tid + s]; }
        __syncthreads();
    }
    if (tid == 0) {
        out[g * 2 + 0] = red0[0] / (float)P2OUT;
        out[g * 2 + 1] = red1[0] / (float)P2OUT;
    }
}

// ---------------- host side ----------------
template <typename T>
static void* sym_addr(T& sym) {
    void* p = nullptr;
    cudaGetSymbolAddress(&p, sym);
    return p;
}

static void split(const float* src, __nv_bfloat16* hi, __nv_bfloat16* lo, long n) {
    long n4 = n / 4;
    split_bf16<<<(int)((n4 + 255) / 256), 256>>>((const float4*)src, (uint2*)hi, (uint2*)lo, n4);
}

static void gemm(const float* A, const __nv_bfloat16* Bhi, const __nv_bfloat16* Blo,
                 const float* bias, float* Cm, int M, int Nc, int K,
                 int validA, int accFlag) {
    dim3 grid((M + BM - 1) / BM, (Nc + BN - 1) / BN);
    gemm_bf16s<<<grid, 256>>>(A, Bhi, Blo, bias, Cm, M, Nc, K, validA, accFlag);
}

extern "C" void kernel_launch(void* const* d_in, const int* in_sizes, int n_in,
                              void* d_out, int out_size) {
    const float* x       = (const float*)d_in[0];
    const int*   ei      = (const int*)d_in[1];
    const float* ew      = (const float*)d_in[2];
    // d_in[3] = batch (unused: batch == arange(N)//L -> reshape)
    const float* ggnn_w  = (const float*)d_in[4];
    const float* wih     = (const float*)d_in[5];
    const float* whh     = (const float*)d_in[6];
    const float* bih     = (const float*)d_in[7];
    const float* bhh     = (const float*)d_in[8];
    const float* conv1_w = (const float*)d_in[9];
    const float* conv1_b = (const float*)d_in[10];
    const float* conv2_w = (const float*)d_in[11];
    const float* conv2_b = (const float*)d_in[12];
    const float* convc1_w = (const float*)d_in[13];
    const float* convc1_b = (const float*)d_in[14];
    const float* convc2_w = (const float*)d_in[15];
    const float* convc2_b = (const float*)d_in[16];
    const float* bn1_g   = (const float*)d_in[17];
    const float* bn1_b   = (const float*)d_in[18];
    const float* bn2_g   = (const float*)d_in[19];
    const float* bn2_b   = (const float*)d_in[20];
    const float* mlpy_w  = (const float*)d_in[21];
    const float* mlpy_b  = (const float*)d_in[22];
    const float* mlpz_w  = (const float*)d_in[23];
    const float* mlpz_b  = (const float*)d_in[24];
    float* out = (float*)d_out;

    float* h    = (float*)sym_addr(g_h);
    float* m    = (float*)sym_addr(g_m);
    float* agg  = (float*)sym_addr(g_agg);
    float* gx   = (float*)sym_addr(g_gx);
    float* gh   = (float*)sym_addr(g_gh);
    float* c    = (float*)sym_addr(g_c);
    float* wT   = (float*)sym_addr(g_wT);
    float* w1p  = (float*)sym_addr(g_w1p);
    float* wc1p = (float*)sym_addr(g_wc1p);
    float* cY1  = (float*)sym_addr(g_convY1);
    float* pY1  = (float*)sym_addr(g_poolY1);
    float* cY2  = (float*)sym_addr(g_convY2);
    float* pY2  = (float*)sym_addr(g_poolY2);
    float* cZ1  = (float*)sym_addr(g_convZ1);
    float* pZ1  = (float*)sym_addr(g_poolZ1);
    float* cZ2  = (float*)sym_addr(g_convZ2);
    float* pZ2  = (float*)sym_addr(g_poolZ2);
    float* st   = (float*)sym_addr(g_stats);
    __nv_bfloat16* wbh = (__nv_bfloat16*)sym_addr(g_wbhi);
    __nv_bfloat16* wbl = (__nv_bfloat16*)sym_addr(g_wblo);
    int* counts = (int*)sym_addr(g_counts);
    int* cursor = (int*)sym_addr(g_cursor);
    int* bsum   = (int*)sym_addr(g_bsum);
    int* rowptr = (int*)sym_addr(g_rowptr);
    int* csrc   = (int*)sym_addr(g_csrc);
    float* cw   = (float*)sym_addr(g_cw);

    const long ND = (long)NN * DD;
    const long ND4 = ND / 4;

    // launches 0-3: first gemm at abs index 3 (ncu capture slot)
    copy_f4<<<(int)((ND4 + 255) / 256), 256>>>((float4*)h, (const float4*)x, ND4);    // 0
    transpose_ggnn<<<(NSTEPS * DD * DD + 255) / 256, 256>>>(ggnn_w, wT);              // 1
    split(wT, wbh + WB_WT, wbl + WB_WT, NSTEPS * DD * DD);                            // 2
    gemm(h, wbh + WB_WT, wbl + WB_WT, nullptr, m, NN, DD, DD, NN, 0);                 // 3 (s=0 m)

    // ---- CSR build (one-time) ----
    fill_zero4<<<(NN / 4 + 255) / 256, 256>>>((float4*)counts, NN / 4);
    hist_kernel<<<EE / 256, 256>>>(ei, counts);
    fill_zero4<<<(NN / 4 + 255) / 256, 256>>>((float4*)cursor, NN / 4);
    scan_block<<<NN / 256, 256>>>(counts, rowptr, bsum);
    scan_bsum<<<1, 256>>>(bsum);
    scan_add<<<NN / 256, 256>>>(rowptr, bsum);
    fill_csr<<<EE / 256, 256>>>(ei, ew, rowptr, cursor, csrc, cw);

    // remaining GGNN weight splits
    split(wih, wbh + WB_WIH, wbl + WB_WIH, 3 * DD * DD);
    split(whh, wbh + WB_WHH, wbl + WB_WHH, 3 * DD * DD);

    // ---- GGNN: 6 steps (s=0 m-gemm already issued above) ----
    for (int s = 0; s < NSTEPS; s++) {
        if (s > 0)
            gemm(h, wbh + WB_WT + s * DD * DD, wbl + WB_WT + s * DD * DD,
                 nullptr, m, NN, DD, DD, NN, 0);
        gather_kernel<<<(int)(((long)NN * 32) / 256), 256>>>(m, rowptr, csrc, cw, agg);
        gemm(agg, wbh + WB_WIH, wbl + WB_WIH, bih, gx, NN, 3 * DD, DD, NN, 0);
        gemm(h, wbh + WB_WHH, wbl + WB_WHH, bhh, gh, NN, 3 * DD, DD, NN, 0);
        gru_kernel<<<(int)((ND4 + 255) / 256), 256>>>((const float4*)gx, (const float4*)gh,
                                                      (float4*)h);
    }

    // c = [h | x]
    concat_kernel<<<(int)((ND4 + 255) / 256), 256>>>((const float4*)h, (const float4*)x,
                                                     (float4*)c);
    // conv weight repacks + splits
    pack_conv3<<<(3 * DD * DD + 255) / 256, 256>>>(conv1_w, w1p, DD);
    pack_conv3<<<(3 * CC * CC + 255) / 256, 256>>>(convc1_w, wc1p, CC);
    split(w1p,      wbh + WB_W1P,  wbl + WB_W1P,  3 * DD * DD);
    split(conv2_w,  wbh + WB_CW2,  wbl + WB_CW2,  DD * DD);
    split(wc1p,     wbh + WB_WC1,  wbl + WB_WC1,  3 * CC * CC);
    split(convc2_w, wbh + WB_CW2C, wbl + WB_CW2C, CC * CC);

    // ---- Y path ----
    gemm(h,          wbh + WB_W1P,               wbl + WB_W1P,               conv1_b,
         cY1, NN, DD, DD, NN, 0);
    gemm(h + DD,     wbh + WB_W1P + DD * DD,     wbl + WB_W1P + DD * DD,     nullptr,
         cY1, NN, DD, DD, NN - 1, 1);
    gemm(h + 2 * DD, wbh + WB_W1P + 2 * DD * DD, wbl + WB_W1P + 2 * DD * DD, nullptr,
         cY1, NN, DD, DD, NN - 2, 1);
    fill_zero4<<<1, 128>>>((float4*)st, 128);
    stats_kernel<<<(GG * L1OUT + 63) / 64, DD>>>(cY1, st, L1OUT, LL, DD, 64);
    bn_relu_pool<<<(int)(((long)GG * P1OUT * DD / 4 + 255) / 256), 256>>>(
        (const float4*)cY1, (float4*)pY1, st, bn1_g, bn1_b, DD, LL, P1OUT, 3, 2,
        1.f / (GG * L1OUT));
    gemm(pY1, wbh + WB_CW2, wbl + WB_CW2, conv2_b, cY2, GG * P1OUT, DD, DD, GG * P1OUT, 0);
    fill_zero4<<<1, 128>>>((float4*)st, 128);
    stats_kernel<<<(GG * P1OUT + 63) / 64, DD>>>(cY2, st, P1OUT, P1OUT, DD, 64);
    bn_relu_pool<<<(int)(((long)GG * P2OUT * DD / 4 + 255) / 256), 256>>>(
        (const float4*)cY2, (float4*)pY2, st, bn1_g, bn1_b, DD, P1OUT, P2OUT, 2, 2,
        1.f / (GG * P1OUT));

    // ---- Z path ----
    gemm(c,          wbh + WB_WC1,               wbl + WB_WC1,               convc1_b,
         cZ1, NN, CC, CC, NN, 0);
    gemm(c + CC,     wbh + WB_WC1 + CC * CC,     wbl + WB_WC1 + CC * CC,     nullptr,
         cZ1, NN, CC, CC, NN - 1, 1);
    gemm(c + 2 * CC, wbh + WB_WC1 + 2 * CC * CC, wbl + WB_WC1 + 2 * CC * CC, nullptr,
         cZ1, NN, CC, CC, NN - 2, 1);
    fill_zero4<<<1, 128>>>((float4*)st, 128);
    stats_kernel<<<(GG * L1OUT + 63) / 64, CC>>>(cZ1, st, L1OUT, LL, CC, 64);
    bn_relu_pool<<<(int)(((long)GG * P1OUT * CC / 4 + 255) / 256), 256>>>(
        (const float4*)cZ1, (float4*)pZ1, st, bn2_g, bn2_b, CC, LL, P1OUT, 3, 2,
        1.f / (GG * L1OUT));
    gemm(pZ1, wbh + WB_CW2C, wbl + WB_CW2C, convc2_b, cZ2, GG * P1OUT, CC, CC, GG * P1OUT, 0);
    fill_zero4<<<1, 128>>>((float4*)st, 128);
    stats_kernel<<<(GG * P1OUT + 63) / 64, CC>>>(cZ2, st, P1OUT, P1OUT, CC, 64);
    bn_relu_pool<<<(int)(((long)GG * P2OUT * CC / 4 + 255) / 256), 256>>>(
        (const float4*)cZ2, (float4*)pZ2, st, bn2_g, bn2_b, CC, P1OUT, P2OUT, 2, 2,
        1.f / (GG * P1OUT));

    // ---- final ----
    final_kernel<<<GG, 128>>>(pY2, pZ2, mlpy_w, mlpy_b, mlpz_w, mlpz_b, out);
}